// round 13
// baseline (speedup 1.0000x reference)
#include <cuda_runtime.h>
#include <cuda_bf16.h>
#include <cstdint>

// ---------------------------------------------------------------------------
// RSSM step, B=32768. Warp-level mma.sync m16n8k16 bf16 (3-term Dekker split),
// ldmatrix.x4 fragment loads, cp.async W staging, double buffer.
// ---------------------------------------------------------------------------

#define BROWS 32768
#define BM 64
#define BN 200
#define KC 32
#define GTHREADS 256     // 8 warps: 4(M) x 2(N)

// smem layout in u32 units
#define AS_P   20                      // A pitch (u32), conflict-free ldmatrix
#define WS_P   20                      // W pitch (u32) per n row (16 used + pad)
#define AS_SZ  (BM * AS_P)             // 1280 u32 per plane
#define WS_SZ  (BN * WS_P)             // 4000 u32 per plane
#define OFF_A(buf, s) (((buf)*2 + (s)) * AS_SZ)
#define OFF_W(buf, s) (4 * AS_SZ + ((buf)*2 + (s)) * WS_SZ)
#define SMEM_U32 (4 * AS_SZ + 4 * WS_SZ)      // 21120
#define SMEM_BYTES (SMEM_U32 * 4)             // 84480

// ---------------- scratch (static device globals; no allocation) -----------
__device__ float g_h  [(size_t)BROWS * 200];
__device__ float g_g  [(size_t)BROWS * 800];
__device__ float g_hp [(size_t)BROWS * 200];
__device__ float g_p  [(size_t)BROWS * 200];
__device__ float g_eps[(size_t)BROWS * 100];
__device__ float g_sm [(size_t)BROWS * 100];
__device__ float g_wgru[400 * 800];

// packed bf16-pair weight planes, N-MAJOR: [N][Kpad/2] u32
#define WP_SA   0                       // 200*80   = 16000
#define WP_GRU  16000                   // 800*208  = 166400
#define WP_BP   182400                  // 200*112  = 22400
#define WP_SP   204800                  // 200*112  = 22400
#define WP_BQ   227200                  // 200*624  = 124800
#define WP_SQ   352000                  // 200*112  = 22400
#define WP_TOTAL 374400
__device__ uint32_t g_wp1[WP_TOTAL];
__device__ uint32_t g_wp2[WP_TOTAL];

// ---------------------------------------------------------------------------
// Threefry-2x32 (partitionable), key = (0, 42)
// ---------------------------------------------------------------------------
#define TFR(r) do { x0 += x1; x1 = (x1 << (r)) | (x1 >> (32 - (r))); x1 ^= x0; } while (0)

__device__ __forceinline__ void threefry2x32_0_42(uint32_t& x0, uint32_t& x1) {
    const uint32_t k0 = 0u;
    const uint32_t k1 = 42u;
    const uint32_t k2 = 0x1BD11BDAu ^ 0u ^ 42u;
    x0 += k0; x1 += k1;
    TFR(13); TFR(15); TFR(26); TFR(6);   x0 += k1; x1 += k2 + 1u;
    TFR(17); TFR(29); TFR(16); TFR(24);  x0 += k2; x1 += k0 + 2u;
    TFR(13); TFR(15); TFR(26); TFR(6);   x0 += k0; x1 += k1 + 3u;
    TFR(17); TFR(29); TFR(16); TFR(24);  x0 += k1; x1 += k2 + 4u;
    TFR(13); TFR(15); TFR(26); TFR(6);   x0 += k2; x1 += k0 + 5u;
}

__device__ __forceinline__ float bits_to_normal(uint32_t bits) {
    float f = __uint_as_float((bits >> 9) | 0x3f800000u) - 1.0f;
    const float lo = -0.99999994f;
    const float range = 2.0f;
    float u = __fadd_rn(__fmul_rn(f, range), lo);
    u = fmaxf(lo, u);
    return __fmul_rn(1.41421356f, erfinvf(u));
}

// ---------------------------------------------------------------------------
// Fused prep: eps (threefry), state*nonterm, GRU weight pack
// ---------------------------------------------------------------------------
#define N_EPS (BROWS * 100)
#define N_PM  (BROWS * 100)
#define N_WG  (400 * 800)

__global__ void prep_kernel(float* __restrict__ eps,
                            const float* __restrict__ st, const float* __restrict__ nt,
                            float* __restrict__ smout,
                            const float* __restrict__ W_ir, const float* __restrict__ W_iz,
                            const float* __restrict__ W_in, const float* __restrict__ W_hr,
                            const float* __restrict__ W_hz, const float* __restrict__ W_hn,
                            float* __restrict__ wg) {
    int i = blockIdx.x * blockDim.x + threadIdx.x;
    if (i < N_EPS) {
        uint32_t x0 = 0u, x1 = (uint32_t)i;
        threefry2x32_0_42(x0, x1);
        eps[i] = bits_to_normal(x0 ^ x1);
        return;
    }
    i -= N_EPS;
    if (i < N_PM) {
        smout[i] = st[i] * nt[i / 100];
        return;
    }
    i -= N_PM;
    if (i < N_WG) {
        int k = i / 800, c = i - k * 800;
        int blk = c / 200, j = c - blk * 200;
        float v = 0.0f;
        if (k < 200) {
            int o = k * 200 + j;
            if (blk == 0) v = W_ir[o];
            else if (blk == 1) v = W_iz[o];
            else if (blk == 2) v = W_in[o];
        } else {
            int o = (k - 200) * 200 + j;
            if (blk == 0) v = W_hr[o];
            else if (blk == 1) v = W_hz[o];
            else if (blk == 3) v = W_hn[o];
        }
        wg[i] = v;
    }
}

// ---------------------------------------------------------------------------
// Pack+split ALL weights, n-major: W[K x N] f32 -> p1/p2 [N][Kpad/2] u32
// ---------------------------------------------------------------------------
__device__ __forceinline__ uint32_t pack2(__nv_bfloat16 lo, __nv_bfloat16 hi) {
    return (uint32_t)__bfloat16_as_ushort(lo) | ((uint32_t)__bfloat16_as_ushort(hi) << 16);
}

struct PsplitArgs {
    const float* W[6];
    int K[6], N[6], ldw[6], Kp2[6];   // Kp2 = Kpad/2
    uint32_t off[6];                   // output plane offset
    uint32_t cum[6];                   // cumulative (N*Kp2) end index
};

__global__ void psplit_all_kernel(PsplitArgs a, uint32_t* __restrict__ p1,
                                  uint32_t* __restrict__ p2) {
    int idx = blockIdx.x * blockDim.x + threadIdx.x;
    if (idx >= (int)a.cum[5]) return;
    int s = 0;
    uint32_t base = 0;
    #pragma unroll
    for (int t = 0; t < 6; t++) {
        if ((uint32_t)idx >= a.cum[t]) { s = t + 1; base = a.cum[t]; }
    }
    int local = idx - (int)base;
    int Kp2 = a.Kp2[s];
    int n = local / Kp2, k2 = local - n * Kp2;
    int k = 2 * k2, K = a.K[s], ldw = a.ldw[s];
    const float* W = a.W[s];
    float v0 = (k     < K) ? W[(size_t)k       * ldw + n] : 0.0f;
    float v1 = (k + 1 < K) ? W[(size_t)(k + 1) * ldw + n] : 0.0f;
    __nv_bfloat16 a0 = __float2bfloat16_rn(v0);
    __nv_bfloat16 a1 = __float2bfloat16_rn(v1);
    __nv_bfloat16 b0 = __float2bfloat16_rn(v0 - __bfloat162float(a0));
    __nv_bfloat16 b1 = __float2bfloat16_rn(v1 - __bfloat162float(a1));
    uint32_t o = a.off[s] + (uint32_t)local;
    p1[o] = pack2(a0, a1);
    p2[o] = pack2(b0, b1);
}

// ---------------------------------------------------------------------------
// mma / ldmatrix / cp.async helpers
// ---------------------------------------------------------------------------
#define MMA_BF16(d, a0, a1, a2, a3, b0, b1)                                   \
    asm volatile(                                                             \
        "mma.sync.aligned.m16n8k16.row.col.f32.bf16.bf16.f32 "                \
        "{%0,%1,%2,%3}, {%4,%5,%6,%7}, {%8,%9}, {%0,%1,%2,%3};"               \
        : "+f"((d)[0]), "+f"((d)[1]), "+f"((d)[2]), "+f"((d)[3])              \
        : "r"(a0), "r"(a1), "r"(a2), "r"(a3), "r"(b0), "r"(b1))

#define LDSM_X4(r0, r1, r2, r3, addr)                                         \
    asm volatile("ldmatrix.sync.aligned.m8n8.x4.shared.b16 {%0,%1,%2,%3}, [%4];" \
        : "=r"(r0), "=r"(r1), "=r"(r2), "=r"(r3) : "r"(addr))

#define CP_ASYNC16(dst_u32addr, src_ptr)                                      \
    asm volatile("cp.async.cg.shared.global [%0], [%1], 16;"                  \
                 :: "r"(dst_u32addr), "l"(src_ptr))
#define CP_COMMIT() asm volatile("cp.async.commit_group;" ::: "memory")
#define CP_WAIT0()  asm volatile("cp.async.wait_group 0;"  ::: "memory")

// ---------------------------------------------------------------------------
// bf16x2 tensor-core GEMM: C[64 x 200/blk] = act(concat(A0,A1) @ W + bias)
// W planes are n-major [N][Kp2]; B frags via ldmatrix.x4 (covers both k-steps).
// ---------------------------------------------------------------------------
template<bool RELU, bool HASBIAS>
__global__ void __launch_bounds__(GTHREADS, 2)
gemm_kernel(const float* __restrict__ A0, const float* __restrict__ A1,
            int c0, int c1, int K, int Kpad,
            const uint32_t* __restrict__ P1, const uint32_t* __restrict__ P2,
            int ldk2,
            const float* __restrict__ bias, float* __restrict__ C, int ldc) {
    extern __shared__ uint32_t su[];
    uint32_t sb;
    asm("{ .reg .u64 t; cvta.to.shared.u64 t, %1; cvt.u32.u64 %0, t; }"
        : "=r"(sb) : "l"(su));

    const int tid  = threadIdx.x;
    const int lane = tid & 31;
    const int wq   = tid >> 5;
    const int mq   = wq >> 1;            // 0..3
    const int nq   = wq & 1;             // 0..1
    const int q    = lane & 3;
    const int row0 = blockIdx.x * BM;
    const int col0 = blockIdx.y * BN;
    const int j0   = nq * 13;
    const int l7   = lane & 7;
    const int th   = lane >> 3;          // ldmatrix tile index 0..3

    // ldmatrix lane-address components
    const int a_row  = mq * 16 + (th & 1) * 8 + l7;  // within 64-row tile
    const int a_k2t  = (th >> 1) * 4;                // 0 or 4
    const int b_k2t  = th * 4;                       // 0,4,8,12 (both k-steps)

    float acc[13][4];
    #pragma unroll
    for (int j = 0; j < 13; j++)
        #pragma unroll
        for (int t = 0; t < 4; t++) acc[j][t] = 0.0f;

    const int ntiles = Kpad / KC;

    // ---- W stage via cp.async: per tile 1600 x 16B (2 splits x 200n x 4 chunks)
    auto stage_w = [&](int tile, int buf) {
        for (int e = tid; e < 1600; e += GTHREADS) {
            int s  = (e >= 800);
            int r  = e - s * 800;
            int n  = r >> 2;
            int ch = r & 3;
            const uint32_t* src = (s ? P2 : P1)
                + (size_t)(col0 + n) * ldk2 + tile * 16 + ch * 4;
            uint32_t dst = sb + (OFF_W(buf, s) + n * WS_P + ch * 4) * 4;
            CP_ASYNC16(dst, src);
        }
    };

    auto stage_a = [&](int k0, int buf) {
        #pragma unroll
        for (int i = 0; i < 4; i++) {
            int e = tid + i * GTHREADS;      // < 1024
            int m = e >> 4, k2 = e & 15;
            int k = k0 + 2 * k2;
            int row = row0 + m;
            float v0 = 0.0f, v1 = 0.0f;
            if (k < K) {
                const float* src = (k < c0) ? (A0 + (size_t)row * c0 + k)
                                            : (A1 + (size_t)row * c1 + (k - c0));
                float2 vv = *(const float2*)src;
                v0 = vv.x; v1 = vv.y;
            }
            __nv_bfloat16 x1 = __float2bfloat16_rn(v0);
            __nv_bfloat16 y1 = __float2bfloat16_rn(v1);
            __nv_bfloat16 x2 = __float2bfloat16_rn(v0 - __bfloat162float(x1));
            __nv_bfloat16 y2 = __float2bfloat16_rn(v1 - __bfloat162float(y1));
            su[OFF_A(buf, 0) + m * AS_P + k2] = pack2(x1, y1);
            su[OFF_A(buf, 1) + m * AS_P + k2] = pack2(x2, y2);
        }
    };

    // ---- prologue: tile 0 ----
    stage_w(0, 0);
    CP_COMMIT();
    stage_a(0, 0);
    CP_WAIT0();
    __syncthreads();

    for (int t = 0; t < ntiles; t++) {
        const int buf = t & 1;
        const bool has_next = (t + 1 < ntiles);

        float2 apf[4];
        if (has_next) {
            stage_w(t + 1, buf ^ 1);
            CP_COMMIT();
            int k0n = (t + 1) * KC;
            #pragma unroll
            for (int i = 0; i < 4; i++) {
                int e = tid + i * GTHREADS;
                int m = e >> 4, k2 = e & 15;
                int k = k0n + 2 * k2;
                int row = row0 + m;
                float2 vv = make_float2(0.0f, 0.0f);
                if (k < K) {
                    const float* src = (k < c0) ? (A0 + (size_t)row * c0 + k)
                                                : (A1 + (size_t)row * c1 + (k - c0));
                    vv = *(const float2*)src;
                }
                apf[i] = vv;
            }
        }

        // ---- A fragments: 4 ldmatrix.x4 (2 splits x 2 k-steps) ----
        uint32_t a1f[2][4], a2f[2][4];
        #pragma unroll
        for (int ks = 0; ks < 2; ks++) {
            uint32_t addr1 = sb + (OFF_A(buf, 0) + a_row * AS_P + ks * 8 + a_k2t) * 4;
            uint32_t addr2 = sb + (OFF_A(buf, 1) + a_row * AS_P + ks * 8 + a_k2t) * 4;
            LDSM_X4(a1f[ks][0], a1f[ks][1], a1f[ks][2], a1f[ks][3], addr1);
            LDSM_X4(a2f[ks][0], a2f[ks][1], a2f[ks][2], a2f[ks][3], addr2);
        }

        // ---- j loop: 2 ldmatrix.x4 (B both k-steps) + 6 MMA ----
        #pragma unroll
        for (int j = 0; j < 13; j++) {
            if (j0 + j < 25) {
                int nrow = (j0 + j) * 8 + l7;
                uint32_t ba1 = sb + (OFF_W(buf, 0) + nrow * WS_P + b_k2t) * 4;
                uint32_t ba2 = sb + (OFF_W(buf, 1) + nrow * WS_P + b_k2t) * 4;
                uint32_t b1_0, b1_1, b1_2, b1_3;   // split1: ks0 b0,b1; ks1 b0,b1
                uint32_t b2_0, b2_1, b2_2, b2_3;   // split2
                LDSM_X4(b1_0, b1_1, b1_2, b1_3, ba1);
                LDSM_X4(b2_0, b2_1, b2_2, b2_3, ba2);
                MMA_BF16(acc[j], a1f[0][0], a1f[0][1], a1f[0][2], a1f[0][3], b1_0, b1_1);
                MMA_BF16(acc[j], a2f[0][0], a2f[0][1], a2f[0][2], a2f[0][3], b1_0, b1_1);
                MMA_BF16(acc[j], a1f[0][0], a1f[0][1], a1f[0][2], a1f[0][3], b2_0, b2_1);
                MMA_BF16(acc[j], a1f[1][0], a1f[1][1], a1f[1][2], a1f[1][3], b1_2, b1_3);
                MMA_BF16(acc[j], a2f[1][0], a2f[1][1], a2f[1][2], a2f[1][3], b1_2, b1_3);
                MMA_BF16(acc[j], a1f[1][0], a1f[1][1], a1f[1][2], a1f[1][3], b2_2, b2_3);
            }
        }

        if (has_next) {
            const int nb = buf ^ 1;
            #pragma unroll
            for (int i = 0; i < 4; i++) {
                int e = tid + i * GTHREADS;
                int m = e >> 4, k2 = e & 15;
                float v0 = apf[i].x, v1 = apf[i].y;
                __nv_bfloat16 x1 = __float2bfloat16_rn(v0);
                __nv_bfloat16 y1 = __float2bfloat16_rn(v1);
                __nv_bfloat16 x2 = __float2bfloat16_rn(v0 - __bfloat162float(x1));
                __nv_bfloat16 y2 = __float2bfloat16_rn(v1 - __bfloat162float(y1));
                su[OFF_A(nb, 0) + m * AS_P + k2] = pack2(x1, y1);
                su[OFF_A(nb, 1) + m * AS_P + k2] = pack2(x2, y2);
            }
        }
        CP_WAIT0();
        __syncthreads();
    }

    // ---- epilogue ----
    const int g = lane >> 2;
    const int r0 = row0 + mq * 16 + g;
    #pragma unroll
    for (int j = 0; j < 13; j++) {
        if (j0 + j < 25) {
            int col = col0 + (j0 + j) * 8 + 2 * q;
            float v0 = acc[j][0], v1 = acc[j][1], v2 = acc[j][2], v3 = acc[j][3];
            if (HASBIAS) {
                float bb0 = bias[col], bb1 = bias[col + 1];
                v0 += bb0; v1 += bb1; v2 += bb0; v3 += bb1;
            }
            if (RELU) {
                v0 = fmaxf(v0, 0.0f); v1 = fmaxf(v1, 0.0f);
                v2 = fmaxf(v2, 0.0f); v3 = fmaxf(v3, 0.0f);
            }
            *(float2*)&C[(size_t)r0 * ldc + col]       = make_float2(v0, v1);
            *(float2*)&C[(size_t)(r0 + 8) * ldc + col] = make_float2(v2, v3);
        }
    }
}

// ---------------------------------------------------------------------------
// GRU combine: belief = (1-z)*n + z*h
// ---------------------------------------------------------------------------
__global__ void gru_combine_kernel(const float* __restrict__ g, const float* __restrict__ h,
                                   const float* __restrict__ b_ir, const float* __restrict__ b_iz,
                                   const float* __restrict__ b_in, const float* __restrict__ b_hn,
                                   float* __restrict__ belief) {
    int i = blockIdx.x * blockDim.x + threadIdx.x;
    if (i >= BROWS * 200) return;
    int b = i / 200, j = i - b * 200;
    const float* gr = g + (size_t)b * 800;
    float r  = 1.0f / (1.0f + expf(-(gr[j]       + b_ir[j])));
    float z  = 1.0f / (1.0f + expf(-(gr[200 + j] + b_iz[j])));
    float nn = tanhf(gr[400 + j] + b_in[j] + r * (gr[600 + j] + b_hn[j]));
    float hv = h[i];
    belief[i] = (1.0f - z) * nn + z * hv;
}

// ---------------------------------------------------------------------------
// Distribution epilogue
// ---------------------------------------------------------------------------
__global__ void dist_kernel(const float* __restrict__ p, const float* __restrict__ eps,
                            float* __restrict__ st, float* __restrict__ mean,
                            float* __restrict__ stddev) {
    int i = blockIdx.x * blockDim.x + threadIdx.x;
    if (i >= BROWS * 100) return;
    int b = i / 100, d = i - b * 100;
    float m   = p[(size_t)b * 200 + d];
    float raw = p[(size_t)b * 200 + 100 + d];
    float sp  = (raw > 0.0f) ? (raw + log1pf(expf(-raw))) : log1pf(expf(raw));
    float s   = sp + 0.1f;
    mean[i]   = m;
    stddev[i] = s;
    st[i]     = m + s * eps[i];
}

// ---------------------------------------------------------------------------
extern "C" void kernel_launch(void* const* d_in, const int* in_sizes, int n_in,
                              void* d_out, int out_size) {
    const float* prev_state   = (const float*)d_in[0];
    const float* prev_action  = (const float*)d_in[1];
    const float* prev_belief  = (const float*)d_in[2];
    const float* observation  = (const float*)d_in[3];
    const float* nonterminals = (const float*)d_in[4];
    const float* W_sa = (const float*)d_in[5];  const float* b_sa = (const float*)d_in[6];
    const float* W_ir = (const float*)d_in[7];  const float* b_ir = (const float*)d_in[8];
    const float* W_iz = (const float*)d_in[9];  const float* b_iz = (const float*)d_in[10];
    const float* W_in = (const float*)d_in[11]; const float* b_in = (const float*)d_in[12];
    const float* W_hr = (const float*)d_in[13];
    const float* W_hz = (const float*)d_in[14];
    const float* W_hn = (const float*)d_in[15]; const float* b_hn = (const float*)d_in[16];
    const float* W_bp = (const float*)d_in[17]; const float* b_bp = (const float*)d_in[18];
    const float* W_sp = (const float*)d_in[19]; const float* b_sp = (const float*)d_in[20];
    const float* W_bq = (const float*)d_in[21]; const float* b_bq = (const float*)d_in[22];
    const float* W_sq = (const float*)d_in[23]; const float* b_sq = (const float*)d_in[24];

    float* out = (float*)d_out;

    float *h, *g, *hp, *p, *eps, *sm, *wgru;
    uint32_t *wp1, *wp2;
    cudaGetSymbolAddress((void**)&h,    g_h);
    cudaGetSymbolAddress((void**)&g,    g_g);
    cudaGetSymbolAddress((void**)&hp,   g_hp);
    cudaGetSymbolAddress((void**)&p,    g_p);
    cudaGetSymbolAddress((void**)&eps,  g_eps);
    cudaGetSymbolAddress((void**)&sm,   g_sm);
    cudaGetSymbolAddress((void**)&wgru, g_wgru);
    cudaGetSymbolAddress((void**)&wp1,  g_wp1);
    cudaGetSymbolAddress((void**)&wp2,  g_wp2);

    cudaFuncSetAttribute(gemm_kernel<true, true>,
                         cudaFuncAttributeMaxDynamicSharedMemorySize, SMEM_BYTES);
    cudaFuncSetAttribute(gemm_kernel<false, false>,
                         cudaFuncAttributeMaxDynamicSharedMemorySize, SMEM_BYTES);

    const size_t oBelief    = 0;
    const size_t oPriorSt   = (size_t)BROWS * 200;
    const size_t oPriorMean = (size_t)BROWS * 300;
    const size_t oPriorStd  = (size_t)BROWS * 400;
    const size_t oPostSt    = (size_t)BROWS * 500;
    const size_t oPostMean  = (size_t)BROWS * 600;
    const size_t oPostStd   = (size_t)BROWS * 700;

    const int MB = BROWS / BM;   // 512 row blocks

    // ---- fused prep (eps + premult + wgru pack) ----
    {
        int total = N_EPS + N_PM + N_WG;
        prep_kernel<<<(total + 255) / 256, 256>>>(
            eps, prev_state, nonterminals, sm,
            W_ir, W_iz, W_in, W_hr, W_hz, W_hn, wgru);
    }

    // ---- single segmented pack+split (n-major planes) ----
    {
        PsplitArgs a;
        const float* Ws[6] = {W_sa, wgru, W_bp, W_sp, W_bq, W_sq};
        int Ks[6]   = {132, 400, 200, 200, 1224, 200};
        int Ns[6]   = {200, 800, 200, 200, 200, 200};
        int lds[6]  = {200, 800, 200, 200, 200, 200};
        int Kp2[6]  = {80, 208, 112, 112, 624, 112};
        uint32_t off[6] = {WP_SA, WP_GRU, WP_BP, WP_SP, WP_BQ, WP_SQ};
        uint32_t cum = 0;
        for (int i = 0; i < 6; i++) {
            a.W[i] = Ws[i]; a.K[i] = Ks[i]; a.N[i] = Ns[i];
            a.ldw[i] = lds[i]; a.Kp2[i] = Kp2[i]; a.off[i] = off[i];
            cum += (uint32_t)(Ns[i] * Kp2[i]);
            a.cum[i] = cum;
        }
        psplit_all_kernel<<<(WP_TOTAL + 255) / 256, 256>>>(a, wp1, wp2);
    }

    // 3) h = relu([sm, action] @ W_sa + b_sa)   (K=132)
    gemm_kernel<true, true><<<dim3(MB, 1), GTHREADS, SMEM_BYTES>>>(
        sm, prev_action, 100, 32, 132, 160, wp1 + WP_SA, wp2 + WP_SA, 80, b_sa, h, 200);

    // 4) g = [prev_belief, h] @ Wgru            (K=400, N=800)
    gemm_kernel<false, false><<<dim3(MB, 4), GTHREADS, SMEM_BYTES>>>(
        prev_belief, h, 200, 200, 400, 416, wp1 + WP_GRU, wp2 + WP_GRU, 208, nullptr, g, 800);

    // 5) new_belief
    gru_combine_kernel<<<(BROWS * 200 + 255) / 256, 256>>>(
        g, h, b_ir, b_iz, b_in, b_hn, out + oBelief);

    // 6) hp = relu(belief @ W_bp + b_bp)        (K=200)
    gemm_kernel<true, true><<<dim3(MB, 1), GTHREADS, SMEM_BYTES>>>(
        out + oBelief, out + oBelief, 200, 200, 200, 224, wp1 + WP_BP, wp2 + WP_BP, 112, b_bp, hp, 200);

    // 7) p = relu(hp @ W_sp + b_sp)             (K=200)
    gemm_kernel<true, true><<<dim3(MB, 1), GTHREADS, SMEM_BYTES>>>(
        hp, hp, 200, 200, 200, 224, wp1 + WP_SP, wp2 + WP_SP, 112, b_sp, p, 200);

    // 8) prior outputs
    dist_kernel<<<(BROWS * 100 + 255) / 256, 256>>>(
        p, eps, out + oPriorSt, out + oPriorMean, out + oPriorStd);

    // 9) hq = relu([belief, obs] @ W_bq + b_bq) (K=1224)
    gemm_kernel<true, true><<<dim3(MB, 1), GTHREADS, SMEM_BYTES>>>(
        out + oBelief, observation, 200, 1024, 1224, 1248, wp1 + WP_BQ, wp2 + WP_BQ, 624, b_bq, hp, 200);

    // 10) p = relu(hq @ W_sq + b_sq)            (K=200)
    gemm_kernel<true, true><<<dim3(MB, 1), GTHREADS, SMEM_BYTES>>>(
        hp, hp, 200, 200, 200, 224, wp1 + WP_SQ, wp2 + WP_SQ, 112, b_sq, p, 200);

    // 11) posterior outputs
    dist_kernel<<<(BROWS * 100 + 255) / 256, 256>>>(
        p, eps, out + oPostSt, out + oPostMean, out + oPostStd);

    (void)in_sizes; (void)n_in; (void)out_size;
}

// round 14
// speedup vs baseline: 1.3125x; 1.3125x over previous
#include <cuda_runtime.h>
#include <cuda_bf16.h>
#include <cstdint>

// ---------------------------------------------------------------------------
// RSSM step, B=32768. Warp-level mma.sync m16n8k16 bf16 (3-term Dekker split),
// scalar-LDS fragments (R11 engine), 512 threads (4Mx4N warps) for occupancy.
// ---------------------------------------------------------------------------

#define BROWS 32768
#define BM 64
#define BN 200
#define KC 32
#define GTHREADS 512     // 16 warps: 4(M) x 4(N)

// smem layout in u32 units
#define AS_P   20                      // A pitch (u32) -> conflict-free frags
#define AS_SZ  (BM * AS_P)             // 1280 u32 per split-plane
#define WS_SZ  (16 * BN)               // 3200 u32 per split-plane (16 k2 rows)
#define OFF_A(buf, s) (((buf)*2 + (s)) * AS_SZ)
#define OFF_W(buf, s) (4 * AS_SZ + ((buf)*2 + (s)) * WS_SZ)
#define SMEM_U32 (4 * AS_SZ + 4 * WS_SZ)      // 17920
#define SMEM_BYTES (SMEM_U32 * 4)             // 71680

// ---------------- scratch (static device globals; no allocation) -----------
__device__ float g_h  [(size_t)BROWS * 200];
__device__ float g_g  [(size_t)BROWS * 800];
__device__ float g_hp [(size_t)BROWS * 200];
__device__ float g_p  [(size_t)BROWS * 200];
__device__ float g_eps[(size_t)BROWS * 100];
__device__ float g_sm [(size_t)BROWS * 100];
__device__ float g_wgru[400 * 800];

// packed bf16-pair weight planes, K-MAJOR: [Kpad/2][N] u32
#define WP_SA   0                       // 80*200   = 16000
#define WP_GRU  16000                   // 208*800  = 166400
#define WP_BP   182400                  // 112*200  = 22400
#define WP_SP   204800                  // 112*200  = 22400
#define WP_BQ   227200                  // 624*200  = 124800
#define WP_SQ   352000                  // 112*200  = 22400
#define WP_TOTAL 374400
__device__ uint32_t g_wp1[WP_TOTAL];
__device__ uint32_t g_wp2[WP_TOTAL];

// ---------------------------------------------------------------------------
// Threefry-2x32 (partitionable), key = (0, 42)
// ---------------------------------------------------------------------------
#define TFR(r) do { x0 += x1; x1 = (x1 << (r)) | (x1 >> (32 - (r))); x1 ^= x0; } while (0)

__device__ __forceinline__ void threefry2x32_0_42(uint32_t& x0, uint32_t& x1) {
    const uint32_t k0 = 0u;
    const uint32_t k1 = 42u;
    const uint32_t k2 = 0x1BD11BDAu ^ 0u ^ 42u;
    x0 += k0; x1 += k1;
    TFR(13); TFR(15); TFR(26); TFR(6);   x0 += k1; x1 += k2 + 1u;
    TFR(17); TFR(29); TFR(16); TFR(24);  x0 += k2; x1 += k0 + 2u;
    TFR(13); TFR(15); TFR(26); TFR(6);   x0 += k0; x1 += k1 + 3u;
    TFR(17); TFR(29); TFR(16); TFR(24);  x0 += k1; x1 += k2 + 4u;
    TFR(13); TFR(15); TFR(26); TFR(6);   x0 += k2; x1 += k0 + 5u;
}

__device__ __forceinline__ float bits_to_normal(uint32_t bits) {
    float f = __uint_as_float((bits >> 9) | 0x3f800000u) - 1.0f;
    const float lo = -0.99999994f;
    const float range = 2.0f;
    float u = __fadd_rn(__fmul_rn(f, range), lo);
    u = fmaxf(lo, u);
    return __fmul_rn(1.41421356f, erfinvf(u));
}

// ---------------------------------------------------------------------------
// Fused prep: eps (threefry), state*nonterm, GRU weight pack
// ---------------------------------------------------------------------------
#define N_EPS (BROWS * 100)
#define N_PM  (BROWS * 100)
#define N_WG  (400 * 800)

__global__ void prep_kernel(float* __restrict__ eps,
                            const float* __restrict__ st, const float* __restrict__ nt,
                            float* __restrict__ smout,
                            const float* __restrict__ W_ir, const float* __restrict__ W_iz,
                            const float* __restrict__ W_in, const float* __restrict__ W_hr,
                            const float* __restrict__ W_hz, const float* __restrict__ W_hn,
                            float* __restrict__ wg) {
    int i = blockIdx.x * blockDim.x + threadIdx.x;
    if (i < N_EPS) {
        uint32_t x0 = 0u, x1 = (uint32_t)i;
        threefry2x32_0_42(x0, x1);
        eps[i] = bits_to_normal(x0 ^ x1);
        return;
    }
    i -= N_EPS;
    if (i < N_PM) {
        smout[i] = st[i] * nt[i / 100];
        return;
    }
    i -= N_PM;
    if (i < N_WG) {
        int k = i / 800, c = i - k * 800;
        int blk = c / 200, j = c - blk * 200;
        float v = 0.0f;
        if (k < 200) {
            int o = k * 200 + j;
            if (blk == 0) v = W_ir[o];
            else if (blk == 1) v = W_iz[o];
            else if (blk == 2) v = W_in[o];
        } else {
            int o = (k - 200) * 200 + j;
            if (blk == 0) v = W_hr[o];
            else if (blk == 1) v = W_hz[o];
            else if (blk == 3) v = W_hn[o];
        }
        wg[i] = v;
    }
}

// ---------------------------------------------------------------------------
// Pack+split ALL weights, k-major: W[K x N] f32 -> p1/p2 [Kpad/2][N] u32
// ---------------------------------------------------------------------------
__device__ __forceinline__ uint32_t pack2(__nv_bfloat16 lo, __nv_bfloat16 hi) {
    return (uint32_t)__bfloat16_as_ushort(lo) | ((uint32_t)__bfloat16_as_ushort(hi) << 16);
}

struct PsplitArgs {
    const float* W[6];
    int K[6], N[6], ldw[6], Kp2[6];
    uint32_t off[6];
    uint32_t cum[6];
};

__global__ void psplit_all_kernel(PsplitArgs a, uint32_t* __restrict__ p1,
                                  uint32_t* __restrict__ p2) {
    int idx = blockIdx.x * blockDim.x + threadIdx.x;
    if (idx >= (int)a.cum[5]) return;
    int s = 0;
    uint32_t base = 0;
    #pragma unroll
    for (int t = 0; t < 6; t++) {
        if ((uint32_t)idx >= a.cum[t]) { s = t + 1; base = a.cum[t]; }
    }
    int local = idx - (int)base;
    int N = a.N[s];
    int k2 = local / N, n = local - k2 * N;
    int k = 2 * k2, K = a.K[s], ldw = a.ldw[s];
    const float* W = a.W[s];
    float v0 = (k     < K) ? W[(size_t)k       * ldw + n] : 0.0f;
    float v1 = (k + 1 < K) ? W[(size_t)(k + 1) * ldw + n] : 0.0f;
    __nv_bfloat16 a0 = __float2bfloat16_rn(v0);
    __nv_bfloat16 a1 = __float2bfloat16_rn(v1);
    __nv_bfloat16 b0 = __float2bfloat16_rn(v0 - __bfloat162float(a0));
    __nv_bfloat16 b1 = __float2bfloat16_rn(v1 - __bfloat162float(a1));
    uint32_t o = a.off[s] + (uint32_t)local;
    p1[o] = pack2(a0, a1);
    p2[o] = pack2(b0, b1);
}

// ---------------------------------------------------------------------------
// mma + cp.async helpers
// ---------------------------------------------------------------------------
#define MMA_BF16(d, a, b0, b1)                                                \
    asm volatile(                                                             \
        "mma.sync.aligned.m16n8k16.row.col.f32.bf16.bf16.f32 "                \
        "{%0,%1,%2,%3}, {%4,%5,%6,%7}, {%8,%9}, {%0,%1,%2,%3};"               \
        : "+f"((d)[0]), "+f"((d)[1]), "+f"((d)[2]), "+f"((d)[3])              \
        : "r"((a)[0]), "r"((a)[1]), "r"((a)[2]), "r"((a)[3]), "r"(b0), "r"(b1))

#define CP_ASYNC16(dst_u32addr, src_ptr)                                      \
    asm volatile("cp.async.cg.shared.global [%0], [%1], 16;"                  \
                 :: "r"(dst_u32addr), "l"(src_ptr))
#define CP_COMMIT() asm volatile("cp.async.commit_group;" ::: "memory")
#define CP_WAIT0()  asm volatile("cp.async.wait_group 0;"  ::: "memory")

// ---------------------------------------------------------------------------
// bf16x2 tensor-core GEMM: C[64 x 200/blk] = act(concat(A0,A1) @ W + bias)
// 16 warps: 4(M, 16 rows each) x 4(N, 7/7/7/4 j-frags). Scalar LDS frags.
// ---------------------------------------------------------------------------
template<bool RELU, bool HASBIAS>
__global__ void __launch_bounds__(GTHREADS, 2)
gemm_kernel(const float* __restrict__ A0, const float* __restrict__ A1,
            int c0, int c1, int K, int Kpad,
            const uint32_t* __restrict__ P1, const uint32_t* __restrict__ P2,
            int ldwp,
            const float* __restrict__ bias, float* __restrict__ C, int ldc) {
    extern __shared__ uint32_t su[];
    uint32_t sb;
    asm("{ .reg .u64 t; cvta.to.shared.u64 t, %1; cvt.u32.u64 %0, t; }"
        : "=r"(sb) : "l"(su));

    const int tid  = threadIdx.x;
    const int lane = tid & 31;
    const int wq   = tid >> 5;           // 0..15
    const int mq   = wq >> 2;            // 0..3
    const int nq   = wq & 3;             // 0..3
    const int g    = lane >> 2;
    const int q    = lane & 3;
    const int row0 = blockIdx.x * BM;
    const int col0 = blockIdx.y * BN;
    const int j0   = nq * 7;             // 0,7,14,21 (last warp: 4 frags)
    const int mrow = mq * 16 + g;

    float acc[7][4];
    #pragma unroll
    for (int j = 0; j < 7; j++)
        #pragma unroll
        for (int t = 0; t < 4; t++) acc[j][t] = 0.0f;

    const int ntiles = Kpad / KC;

    // ---- W stage via cp.async: 1600 uint4 per tile (2 splits x 800) ----
    auto stage_w = [&](int tile, int buf) {
        for (int e = tid; e < 1600; e += GTHREADS) {
            int s   = (e >= 800);
            int r   = e - s * 800;
            int k2  = r / 50;
            int n4  = (r - k2 * 50) * 4;
            const uint32_t* src = (s ? P2 : P1)
                + (size_t)(tile * 16 + k2) * ldwp + col0 + n4;
            uint32_t dst = sb + (OFF_W(buf, s) + k2 * BN + n4) * 4;
            CP_ASYNC16(dst, src);
        }
    };

    // ---- prologue: tile 0 ----
    stage_w(0, 0);
    CP_COMMIT();
    #pragma unroll
    for (int i = 0; i < 2; i++) {
        int e = tid + i * GTHREADS;      // < 1024
        int m = e >> 4, k2 = e & 15;
        int k = 2 * k2;
        int row = row0 + m;
        float v0 = 0.0f, v1 = 0.0f;
        if (k < K) {
            const float* src = (k < c0) ? (A0 + (size_t)row * c0 + k)
                                        : (A1 + (size_t)row * c1 + (k - c0));
            float2 vv = *(const float2*)src;
            v0 = vv.x; v1 = vv.y;
        }
        __nv_bfloat16 x1 = __float2bfloat16_rn(v0);
        __nv_bfloat16 y1 = __float2bfloat16_rn(v1);
        __nv_bfloat16 x2 = __float2bfloat16_rn(v0 - __bfloat162float(x1));
        __nv_bfloat16 y2 = __float2bfloat16_rn(v1 - __bfloat162float(y1));
        su[OFF_A(0, 0) + m * AS_P + k2] = pack2(x1, y1);
        su[OFF_A(0, 1) + m * AS_P + k2] = pack2(x2, y2);
    }
    CP_WAIT0();
    __syncthreads();

    for (int t = 0; t < ntiles; t++) {
        const int buf = t & 1;
        const bool has_next = (t + 1 < ntiles);

        float2 apf[2];
        if (has_next) {
            stage_w(t + 1, buf ^ 1);
            CP_COMMIT();
            int k0n = (t + 1) * KC;
            #pragma unroll
            for (int i = 0; i < 2; i++) {
                int e = tid + i * GTHREADS;
                int m = e >> 4, k2 = e & 15;
                int k = k0n + 2 * k2;
                int row = row0 + m;
                float2 vv = make_float2(0.0f, 0.0f);
                if (k < K) {
                    const float* src = (k < c0) ? (A0 + (size_t)row * c0 + k)
                                                : (A1 + (size_t)row * c1 + (k - c0));
                    vv = *(const float2*)src;
                }
                apf[i] = vv;
            }
        }

        // ---- compute from smem[buf] ----
        const uint32_t* A1s = su + OFF_A(buf, 0);
        const uint32_t* A2s = su + OFF_A(buf, 1);
        const uint32_t* W1s = su + OFF_W(buf, 0);
        const uint32_t* W2s = su + OFF_W(buf, 1);
        #pragma unroll
        for (int ks = 0; ks < 2; ks++) {
            const int kb = ks * 8;
            uint32_t a1[4], a2[4];
            a1[0] = A1s[mrow * AS_P + kb + q];
            a1[1] = A1s[(mrow + 8) * AS_P + kb + q];
            a1[2] = A1s[mrow * AS_P + kb + q + 4];
            a1[3] = A1s[(mrow + 8) * AS_P + kb + q + 4];
            a2[0] = A2s[mrow * AS_P + kb + q];
            a2[1] = A2s[(mrow + 8) * AS_P + kb + q];
            a2[2] = A2s[mrow * AS_P + kb + q + 4];
            a2[3] = A2s[(mrow + 8) * AS_P + kb + q + 4];
            #pragma unroll
            for (int j = 0; j < 7; j++) {
                if (j0 + j < 25) {
                    int n = (j0 + j) * 8 + g;
                    uint32_t b10 = W1s[(kb + q) * BN + n];
                    uint32_t b11 = W1s[(kb + q + 4) * BN + n];
                    uint32_t b20 = W2s[(kb + q) * BN + n];
                    uint32_t b21 = W2s[(kb + q + 4) * BN + n];
                    MMA_BF16(acc[j], a1, b10, b11);   // a1*b1
                    MMA_BF16(acc[j], a2, b10, b11);   // a2*b1
                    MMA_BF16(acc[j], a1, b20, b21);   // a1*b2
                }
            }
        }

        if (has_next) {
            const int nb = buf ^ 1;
            #pragma unroll
            for (int i = 0; i < 2; i++) {
                int e = tid + i * GTHREADS;
                int m = e >> 4, k2 = e & 15;
                float v0 = apf[i].x, v1 = apf[i].y;
                __nv_bfloat16 x1 = __float2bfloat16_rn(v0);
                __nv_bfloat16 y1 = __float2bfloat16_rn(v1);
                __nv_bfloat16 x2 = __float2bfloat16_rn(v0 - __bfloat162float(x1));
                __nv_bfloat16 y2 = __float2bfloat16_rn(v1 - __bfloat162float(y1));
                su[OFF_A(nb, 0) + m * AS_P + k2] = pack2(x1, y1);
                su[OFF_A(nb, 1) + m * AS_P + k2] = pack2(x2, y2);
            }
        }
        CP_WAIT0();
        __syncthreads();
    }

    // ---- epilogue ----
    const int r0 = row0 + mrow;
    #pragma unroll
    for (int j = 0; j < 7; j++) {
        if (j0 + j < 25) {
            int col = col0 + (j0 + j) * 8 + 2 * q;
            float v0 = acc[j][0], v1 = acc[j][1], v2 = acc[j][2], v3 = acc[j][3];
            if (HASBIAS) {
                float bb0 = bias[col], bb1 = bias[col + 1];
                v0 += bb0; v1 += bb1; v2 += bb0; v3 += bb1;
            }
            if (RELU) {
                v0 = fmaxf(v0, 0.0f); v1 = fmaxf(v1, 0.0f);
                v2 = fmaxf(v2, 0.0f); v3 = fmaxf(v3, 0.0f);
            }
            *(float2*)&C[(size_t)r0 * ldc + col]       = make_float2(v0, v1);
            *(float2*)&C[(size_t)(r0 + 8) * ldc + col] = make_float2(v2, v3);
        }
    }
}

// ---------------------------------------------------------------------------
// GRU combine: belief = (1-z)*n + z*h
// ---------------------------------------------------------------------------
__global__ void gru_combine_kernel(const float* __restrict__ g, const float* __restrict__ h,
                                   const float* __restrict__ b_ir, const float* __restrict__ b_iz,
                                   const float* __restrict__ b_in, const float* __restrict__ b_hn,
                                   float* __restrict__ belief) {
    int i = blockIdx.x * blockDim.x + threadIdx.x;
    if (i >= BROWS * 200) return;
    int b = i / 200, j = i - b * 200;
    const float* gr = g + (size_t)b * 800;
    float r  = 1.0f / (1.0f + expf(-(gr[j]       + b_ir[j])));
    float z  = 1.0f / (1.0f + expf(-(gr[200 + j] + b_iz[j])));
    float nn = tanhf(gr[400 + j] + b_in[j] + r * (gr[600 + j] + b_hn[j]));
    float hv = h[i];
    belief[i] = (1.0f - z) * nn + z * hv;
}

// ---------------------------------------------------------------------------
// Distribution epilogue
// ---------------------------------------------------------------------------
__global__ void dist_kernel(const float* __restrict__ p, const float* __restrict__ eps,
                            float* __restrict__ st, float* __restrict__ mean,
                            float* __restrict__ stddev) {
    int i = blockIdx.x * blockDim.x + threadIdx.x;
    if (i >= BROWS * 100) return;
    int b = i / 100, d = i - b * 100;
    float m   = p[(size_t)b * 200 + d];
    float raw = p[(size_t)b * 200 + 100 + d];
    float sp  = (raw > 0.0f) ? (raw + log1pf(expf(-raw))) : log1pf(expf(raw));
    float s   = sp + 0.1f;
    mean[i]   = m;
    stddev[i] = s;
    st[i]     = m + s * eps[i];
}

// ---------------------------------------------------------------------------
extern "C" void kernel_launch(void* const* d_in, const int* in_sizes, int n_in,
                              void* d_out, int out_size) {
    const float* prev_state   = (const float*)d_in[0];
    const float* prev_action  = (const float*)d_in[1];
    const float* prev_belief  = (const float*)d_in[2];
    const float* observation  = (const float*)d_in[3];
    const float* nonterminals = (const float*)d_in[4];
    const float* W_sa = (const float*)d_in[5];  const float* b_sa = (const float*)d_in[6];
    const float* W_ir = (const float*)d_in[7];  const float* b_ir = (const float*)d_in[8];
    const float* W_iz = (const float*)d_in[9];  const float* b_iz = (const float*)d_in[10];
    const float* W_in = (const float*)d_in[11]; const float* b_in = (const float*)d_in[12];
    const float* W_hr = (const float*)d_in[13];
    const float* W_hz = (const float*)d_in[14];
    const float* W_hn = (const float*)d_in[15]; const float* b_hn = (const float*)d_in[16];
    const float* W_bp = (const float*)d_in[17]; const float* b_bp = (const float*)d_in[18];
    const float* W_sp = (const float*)d_in[19]; const float* b_sp = (const float*)d_in[20];
    const float* W_bq = (const float*)d_in[21]; const float* b_bq = (const float*)d_in[22];
    const float* W_sq = (const float*)d_in[23]; const float* b_sq = (const float*)d_in[24];

    float* out = (float*)d_out;

    float *h, *g, *hp, *p, *eps, *sm, *wgru;
    uint32_t *wp1, *wp2;
    cudaGetSymbolAddress((void**)&h,    g_h);
    cudaGetSymbolAddress((void**)&g,    g_g);
    cudaGetSymbolAddress((void**)&hp,   g_hp);
    cudaGetSymbolAddress((void**)&p,    g_p);
    cudaGetSymbolAddress((void**)&eps,  g_eps);
    cudaGetSymbolAddress((void**)&sm,   g_sm);
    cudaGetSymbolAddress((void**)&wgru, g_wgru);
    cudaGetSymbolAddress((void**)&wp1,  g_wp1);
    cudaGetSymbolAddress((void**)&wp2,  g_wp2);

    cudaFuncSetAttribute(gemm_kernel<true, true>,
                         cudaFuncAttributeMaxDynamicSharedMemorySize, SMEM_BYTES);
    cudaFuncSetAttribute(gemm_kernel<false, false>,
                         cudaFuncAttributeMaxDynamicSharedMemorySize, SMEM_BYTES);

    const size_t oBelief    = 0;
    const size_t oPriorSt   = (size_t)BROWS * 200;
    const size_t oPriorMean = (size_t)BROWS * 300;
    const size_t oPriorStd  = (size_t)BROWS * 400;
    const size_t oPostSt    = (size_t)BROWS * 500;
    const size_t oPostMean  = (size_t)BROWS * 600;
    const size_t oPostStd   = (size_t)BROWS * 700;

    const int MB = BROWS / BM;   // 512 row blocks

    // ---- fused prep (eps + premult + wgru pack) ----
    {
        int total = N_EPS + N_PM + N_WG;
        prep_kernel<<<(total + 255) / 256, 256>>>(
            eps, prev_state, nonterminals, sm,
            W_ir, W_iz, W_in, W_hr, W_hz, W_hn, wgru);
    }

    // ---- single segmented pack+split (k-major planes) ----
    {
        PsplitArgs a;
        const float* Ws[6] = {W_sa, wgru, W_bp, W_sp, W_bq, W_sq};
        int Ks[6]   = {132, 400, 200, 200, 1224, 200};
        int Ns[6]   = {200, 800, 200, 200, 200, 200};
        int lds[6]  = {200, 800, 200, 200, 200, 200};
        int Kp2[6]  = {80, 208, 112, 112, 624, 112};
        uint32_t off[6] = {WP_SA, WP_GRU, WP_BP, WP_SP, WP_BQ, WP_SQ};
        uint32_t cum = 0;
        for (int i = 0; i < 6; i++) {
            a.W[i] = Ws[i]; a.K[i] = Ks[i]; a.N[i] = Ns[i];
            a.ldw[i] = lds[i]; a.Kp2[i] = Kp2[i]; a.off[i] = off[i];
            cum += (uint32_t)(Ns[i] * Kp2[i]);
            a.cum[i] = cum;
        }
        psplit_all_kernel<<<(WP_TOTAL + 255) / 256, 256>>>(a, wp1, wp2);
    }

    // 3) h = relu([sm, action] @ W_sa + b_sa)   (K=132)
    gemm_kernel<true, true><<<dim3(MB, 1), GTHREADS, SMEM_BYTES>>>(
        sm, prev_action, 100, 32, 132, 160, wp1 + WP_SA, wp2 + WP_SA, 200, b_sa, h, 200);

    // 4) g = [prev_belief, h] @ Wgru            (K=400, N=800)
    gemm_kernel<false, false><<<dim3(MB, 4), GTHREADS, SMEM_BYTES>>>(
        prev_belief, h, 200, 200, 400, 416, wp1 + WP_GRU, wp2 + WP_GRU, 800, nullptr, g, 800);

    // 5) new_belief
    gru_combine_kernel<<<(BROWS * 200 + 255) / 256, 256>>>(
        g, h, b_ir, b_iz, b_in, b_hn, out + oBelief);

    // 6) hp = relu(belief @ W_bp + b_bp)        (K=200)
    gemm_kernel<true, true><<<dim3(MB, 1), GTHREADS, SMEM_BYTES>>>(
        out + oBelief, out + oBelief, 200, 200, 200, 224, wp1 + WP_BP, wp2 + WP_BP, 200, b_bp, hp, 200);

    // 7) p = relu(hp @ W_sp + b_sp)             (K=200)
    gemm_kernel<true, true><<<dim3(MB, 1), GTHREADS, SMEM_BYTES>>>(
        hp, hp, 200, 200, 200, 224, wp1 + WP_SP, wp2 + WP_SP, 200, b_sp, p, 200);

    // 8) prior outputs
    dist_kernel<<<(BROWS * 100 + 255) / 256, 256>>>(
        p, eps, out + oPriorSt, out + oPriorMean, out + oPriorStd);

    // 9) hq = relu([belief, obs] @ W_bq + b_bq) (K=1224)
    gemm_kernel<true, true><<<dim3(MB, 1), GTHREADS, SMEM_BYTES>>>(
        out + oBelief, observation, 200, 1024, 1224, 1248, wp1 + WP_BQ, wp2 + WP_BQ, 200, b_bq, hp, 200);

    // 10) p = relu(hq @ W_sq + b_sq)            (K=200)
    gemm_kernel<true, true><<<dim3(MB, 1), GTHREADS, SMEM_BYTES>>>(
        hp, hp, 200, 200, 200, 224, wp1 + WP_SQ, wp2 + WP_SQ, 200, b_sq, p, 200);

    // 11) posterior outputs
    dist_kernel<<<(BROWS * 100 + 255) / 256, 256>>>(
        p, eps, out + oPostSt, out + oPostMean, out + oPostStd);

    (void)in_sizes; (void)n_in; (void)out_size;
}

// round 15
// speedup vs baseline: 1.3220x; 1.0073x over previous
#include <cuda_runtime.h>
#include <cuda_bf16.h>
#include <cstdint>

// ---------------------------------------------------------------------------
// RSSM step, B=32768. Warp-level mma.sync m16n8k16 bf16 (3-term Dekker split),
// fragment-order u64 weight pairs (1 LDS.64 per B fragment), cp.async staging,
// double buffer, 512 threads (4Mx4N warps).
// ---------------------------------------------------------------------------

#define BROWS 32768
#define BM 64
#define BN 200
#define KC 32
#define GTHREADS 512     // 16 warps: 4(M) x 4(N)

// smem layout in u32 units
#define AS_P   20                      // A pitch (u32) -> conflict-free frags
#define AS_SZ  (BM * AS_P)             // 1280 u32 per split-plane
#define WS_PITCH 204                   // u64 pitch per f-row (bank-pair friendly)
#define WS_SZ  (8 * WS_PITCH * 2)      // 3264 u32 per plane (8 f-rows of u64)
#define OFF_A(buf, s) (((buf)*2 + (s)) * AS_SZ)
#define OFF_W(buf, s) (4 * AS_SZ + ((buf)*2 + (s)) * WS_SZ)
#define SMEM_U32 (4 * AS_SZ + 4 * WS_SZ)      // 18176
#define SMEM_BYTES (SMEM_U32 * 4)             // 72704

// ---------------- scratch (static device globals; no allocation) -----------
__device__ float g_h  [(size_t)BROWS * 200];
__device__ float g_g  [(size_t)BROWS * 800];
__device__ float g_hp [(size_t)BROWS * 200];
__device__ float g_p  [(size_t)BROWS * 200];
__device__ float g_eps[(size_t)BROWS * 100];
__device__ float g_sm [(size_t)BROWS * 100];
__device__ float g_wgru[400 * 800];

// fragment-order packed weight planes (u64 entries, stored as u32 array):
// per k-tile (32 k = 16 k2), 8 f-rows, N entries; entry = (k2a, k2a+4) pair
#define WP_SA   0                       // 160*200/2  = 16000 u32
#define WP_GRU  16000                   // 416*800/2  = 166400
#define WP_BP   182400                  // 224*200/2  = 22400
#define WP_SP   204800
#define WP_BQ   227200                  // 1248*200/2 = 124800
#define WP_SQ   352000
#define WP_TOTAL 374400
__device__ uint32_t g_wp1[WP_TOTAL];
__device__ uint32_t g_wp2[WP_TOTAL];

// ---------------------------------------------------------------------------
// Threefry-2x32 (partitionable), key = (0, 42)
// ---------------------------------------------------------------------------
#define TFR(r) do { x0 += x1; x1 = (x1 << (r)) | (x1 >> (32 - (r))); x1 ^= x0; } while (0)

__device__ __forceinline__ void threefry2x32_0_42(uint32_t& x0, uint32_t& x1) {
    const uint32_t k0 = 0u;
    const uint32_t k1 = 42u;
    const uint32_t k2 = 0x1BD11BDAu ^ 0u ^ 42u;
    x0 += k0; x1 += k1;
    TFR(13); TFR(15); TFR(26); TFR(6);   x0 += k1; x1 += k2 + 1u;
    TFR(17); TFR(29); TFR(16); TFR(24);  x0 += k2; x1 += k0 + 2u;
    TFR(13); TFR(15); TFR(26); TFR(6);   x0 += k0; x1 += k1 + 3u;
    TFR(17); TFR(29); TFR(16); TFR(24);  x0 += k1; x1 += k2 + 4u;
    TFR(13); TFR(15); TFR(26); TFR(6);   x0 += k2; x1 += k0 + 5u;
}

__device__ __forceinline__ float bits_to_normal(uint32_t bits) {
    float f = __uint_as_float((bits >> 9) | 0x3f800000u) - 1.0f;
    const float lo = -0.99999994f;
    const float range = 2.0f;
    float u = __fadd_rn(__fmul_rn(f, range), lo);
    u = fmaxf(lo, u);
    return __fmul_rn(1.41421356f, erfinvf(u));
}

// ---------------------------------------------------------------------------
// Fused prep: eps (threefry), state*nonterm, GRU weight pack
// ---------------------------------------------------------------------------
#define N_EPS (BROWS * 100)
#define N_PM  (BROWS * 100)
#define N_WG  (400 * 800)

__global__ void prep_kernel(float* __restrict__ eps,
                            const float* __restrict__ st, const float* __restrict__ nt,
                            float* __restrict__ smout,
                            const float* __restrict__ W_ir, const float* __restrict__ W_iz,
                            const float* __restrict__ W_in, const float* __restrict__ W_hr,
                            const float* __restrict__ W_hz, const float* __restrict__ W_hn,
                            float* __restrict__ wg) {
    int i = blockIdx.x * blockDim.x + threadIdx.x;
    if (i < N_EPS) {
        uint32_t x0 = 0u, x1 = (uint32_t)i;
        threefry2x32_0_42(x0, x1);
        eps[i] = bits_to_normal(x0 ^ x1);
        return;
    }
    i -= N_EPS;
    if (i < N_PM) {
        smout[i] = st[i] * nt[i / 100];
        return;
    }
    i -= N_PM;
    if (i < N_WG) {
        int k = i / 800, c = i - k * 800;
        int blk = c / 200, j = c - blk * 200;
        float v = 0.0f;
        if (k < 200) {
            int o = k * 200 + j;
            if (blk == 0) v = W_ir[o];
            else if (blk == 1) v = W_iz[o];
            else if (blk == 2) v = W_in[o];
        } else {
            int o = (k - 200) * 200 + j;
            if (blk == 0) v = W_hr[o];
            else if (blk == 1) v = W_hz[o];
            else if (blk == 3) v = W_hn[o];
        }
        wg[i] = v;
    }
}

// ---------------------------------------------------------------------------
// Pack+split ALL weights into fragment-order u64 planes.
// Entry (segment s, u64 index local): n = local % N, rf = local / N,
// t = rf/8, f = rf%8, k2a = t*16 + (f>>2)*8 + (f&3), k2b = k2a + 4.
// u64 = (pack(k2b) << 32) | pack(k2a); plane1 = hi bf16 split, plane2 = lo.
// ---------------------------------------------------------------------------
__device__ __forceinline__ uint32_t pack2(__nv_bfloat16 lo, __nv_bfloat16 hi) {
    return (uint32_t)__bfloat16_as_ushort(lo) | ((uint32_t)__bfloat16_as_ushort(hi) << 16);
}

struct PsplitArgs {
    const float* W[6];
    int K[6], N[6], ldw[6];
    uint32_t off[6];    // u32 offsets
    uint32_t cum[6];    // cumulative u64 entry counts
};

__global__ void psplit_all_kernel(PsplitArgs a, uint32_t* __restrict__ p1,
                                  uint32_t* __restrict__ p2) {
    int idx = blockIdx.x * blockDim.x + threadIdx.x;
    if (idx >= (int)a.cum[5]) return;
    int s = 0;
    uint32_t base = 0;
    #pragma unroll
    for (int t = 0; t < 6; t++) {
        if ((uint32_t)idx >= a.cum[t]) { s = t + 1; base = a.cum[t]; }
    }
    int local = idx - (int)base;
    int N = a.N[s], K = a.K[s], ldw = a.ldw[s];
    const float* W = a.W[s];
    int n  = local % N;
    int rf = local / N;
    int t  = rf >> 3, f = rf & 7;
    int k2a = t * 16 + ((f >> 2) << 3) + (f & 3);

    uint32_t v1[2], v2[2];
    #pragma unroll
    for (int half = 0; half < 2; half++) {
        int k2 = k2a + half * 4;
        int k = 2 * k2;
        float w0 = (k     < K) ? W[(size_t)k       * ldw + n] : 0.0f;
        float w1 = (k + 1 < K) ? W[(size_t)(k + 1) * ldw + n] : 0.0f;
        __nv_bfloat16 a0 = __float2bfloat16_rn(w0);
        __nv_bfloat16 a1 = __float2bfloat16_rn(w1);
        __nv_bfloat16 b0 = __float2bfloat16_rn(w0 - __bfloat162float(a0));
        __nv_bfloat16 b1 = __float2bfloat16_rn(w1 - __bfloat162float(a1));
        v1[half] = pack2(a0, a1);
        v2[half] = pack2(b0, b1);
    }
    ((uint2*)(p1 + a.off[s]))[local] = make_uint2(v1[0], v1[1]);
    ((uint2*)(p2 + a.off[s]))[local] = make_uint2(v2[0], v2[1]);
}

// ---------------------------------------------------------------------------
// mma + cp.async helpers
// ---------------------------------------------------------------------------
#define MMA_BF16(d, a, b0, b1)                                                \
    asm volatile(                                                             \
        "mma.sync.aligned.m16n8k16.row.col.f32.bf16.bf16.f32 "                \
        "{%0,%1,%2,%3}, {%4,%5,%6,%7}, {%8,%9}, {%0,%1,%2,%3};"               \
        : "+f"((d)[0]), "+f"((d)[1]), "+f"((d)[2]), "+f"((d)[3])              \
        : "r"((a)[0]), "r"((a)[1]), "r"((a)[2]), "r"((a)[3]), "r"(b0), "r"(b1))

#define CP_ASYNC16(dst_u32addr, src_ptr)                                      \
    asm volatile("cp.async.cg.shared.global [%0], [%1], 16;"                  \
                 :: "r"(dst_u32addr), "l"(src_ptr))
#define CP_COMMIT() asm volatile("cp.async.commit_group;" ::: "memory")
#define CP_WAIT0()  asm volatile("cp.async.wait_group 0;"  ::: "memory")

// ---------------------------------------------------------------------------
// bf16x2 tensor-core GEMM: C[64 x 200/blk] = act(concat(A0,A1) @ W + bias)
// 16 warps: 4(M) x 4(N, 7/7/7/4 j-frags). B frags: one LDS.64 each.
// Nw = full N of the weight matrix (for gmem addressing of its planes).
// ---------------------------------------------------------------------------
template<bool RELU, bool HASBIAS>
__global__ void __launch_bounds__(GTHREADS, 2)
gemm_kernel(const float* __restrict__ A0, const float* __restrict__ A1,
            int c0, int c1, int K, int Kpad,
            const uint32_t* __restrict__ P1, const uint32_t* __restrict__ P2,
            int Nw,
            const float* __restrict__ bias, float* __restrict__ C, int ldc) {
    extern __shared__ uint32_t su[];
    uint32_t sb;
    asm("{ .reg .u64 t; cvta.to.shared.u64 t, %1; cvt.u32.u64 %0, t; }"
        : "=r"(sb) : "l"(su));

    const int tid  = threadIdx.x;
    const int lane = tid & 31;
    const int wq   = tid >> 5;           // 0..15
    const int mq   = wq >> 2;            // 0..3
    const int nq   = wq & 3;             // 0..3
    const int g    = lane >> 2;
    const int q    = lane & 3;
    const int row0 = blockIdx.x * BM;
    const int col0 = blockIdx.y * BN;
    const int j0   = nq * 7;             // 0,7,14,21 (last warp: 4 frags)
    const int mrow = mq * 16 + g;

    float acc[7][4];
    #pragma unroll
    for (int j = 0; j < 7; j++)
        #pragma unroll
        for (int t = 0; t < 4; t++) acc[j][t] = 0.0f;

    const int ntiles = Kpad / KC;

    // ---- W stage via cp.async: 1600 x 16B per tile (2 planes x 8f x 100 pairs)
    auto stage_w = [&](int tile, int buf) {
        for (int e = tid; e < 1600; e += GTHREADS) {
            int s     = (e >= 800);
            int r     = e - s * 800;
            int f     = r / 100;
            int npair = r - f * 100;
            const uint32_t* src = (s ? P2 : P1)
                + (size_t)(tile * 8 + f) * Nw * 2 + (col0 + npair * 2) * 2;
            uint32_t dst = sb + (OFF_W(buf, s) + f * (WS_PITCH * 2) + npair * 4) * 4;
            CP_ASYNC16(dst, src);
        }
    };

    auto stage_a_regs = [&](int k0, float2* apf) {
        #pragma unroll
        for (int i = 0; i < 2; i++) {
            int e = tid + i * GTHREADS;
            int m = e >> 4, k2 = e & 15;
            int k = k0 + 2 * k2;
            int row = row0 + m;
            float2 vv = make_float2(0.0f, 0.0f);
            if (k < K) {
                const float* src = (k < c0) ? (A0 + (size_t)row * c0 + k)
                                            : (A1 + (size_t)row * c1 + (k - c0));
                vv = *(const float2*)src;
            }
            apf[i] = vv;
        }
    };
    auto store_a = [&](const float2* apf, int buf) {
        #pragma unroll
        for (int i = 0; i < 2; i++) {
            int e = tid + i * GTHREADS;
            int m = e >> 4, k2 = e & 15;
            float v0 = apf[i].x, v1 = apf[i].y;
            __nv_bfloat16 x1 = __float2bfloat16_rn(v0);
            __nv_bfloat16 y1 = __float2bfloat16_rn(v1);
            __nv_bfloat16 x2 = __float2bfloat16_rn(v0 - __bfloat162float(x1));
            __nv_bfloat16 y2 = __float2bfloat16_rn(v1 - __bfloat162float(y1));
            su[OFF_A(buf, 0) + m * AS_P + k2] = pack2(x1, y1);
            su[OFF_A(buf, 1) + m * AS_P + k2] = pack2(x2, y2);
        }
    };

    // ---- prologue: tile 0 ----
    stage_w(0, 0);
    CP_COMMIT();
    {
        float2 apf[2];
        stage_a_regs(0, apf);
        store_a(apf, 0);
    }
    CP_WAIT0();
    __syncthreads();

    for (int t = 0; t < ntiles; t++) {
        const int buf = t & 1;
        const bool has_next = (t + 1 < ntiles);

        float2 apf[2];
        if (has_next) {
            stage_w(t + 1, buf ^ 1);
            CP_COMMIT();
            stage_a_regs((t + 1) * KC, apf);
        }

        // ---- compute from smem[buf] ----
        const uint32_t* A1s = su + OFF_A(buf, 0);
        const uint32_t* A2s = su + OFF_A(buf, 1);
        const uint2* W1p = (const uint2*)(su + OFF_W(buf, 0));
        const uint2* W2p = (const uint2*)(su + OFF_W(buf, 1));
        #pragma unroll
        for (int ks = 0; ks < 2; ks++) {
            const int kb = ks * 8;
            const int fb = (ks * 4 + q) * WS_PITCH;
            uint32_t a1[4], a2[4];
            a1[0] = A1s[mrow * AS_P + kb + q];
            a1[1] = A1s[(mrow + 8) * AS_P + kb + q];
            a1[2] = A1s[mrow * AS_P + kb + q + 4];
            a1[3] = A1s[(mrow + 8) * AS_P + kb + q + 4];
            a2[0] = A2s[mrow * AS_P + kb + q];
            a2[1] = A2s[(mrow + 8) * AS_P + kb + q];
            a2[2] = A2s[mrow * AS_P + kb + q + 4];
            a2[3] = A2s[(mrow + 8) * AS_P + kb + q + 4];
            #pragma unroll
            for (int j = 0; j < 7; j++) {
                if (j0 + j < 25) {
                    int n = (j0 + j) * 8 + g;
                    uint2 b1v = W1p[fb + n];
                    uint2 b2v = W2p[fb + n];
                    MMA_BF16(acc[j], a1, b1v.x, b1v.y);   // a1*b1
                    MMA_BF16(acc[j], a2, b1v.x, b1v.y);   // a2*b1
                    MMA_BF16(acc[j], a1, b2v.x, b2v.y);   // a1*b2
                }
            }
        }

        if (has_next) {
            const int nb = buf ^ 1;
            store_a(apf, nb);
        }
        CP_WAIT0();
        __syncthreads();
    }

    // ---- epilogue ----
    const int r0 = row0 + mrow;
    #pragma unroll
    for (int j = 0; j < 7; j++) {
        if (j0 + j < 25) {
            int col = col0 + (j0 + j) * 8 + 2 * q;
            float v0 = acc[j][0], v1 = acc[j][1], v2 = acc[j][2], v3 = acc[j][3];
            if (HASBIAS) {
                float bb0 = bias[col], bb1 = bias[col + 1];
                v0 += bb0; v1 += bb1; v2 += bb0; v3 += bb1;
            }
            if (RELU) {
                v0 = fmaxf(v0, 0.0f); v1 = fmaxf(v1, 0.0f);
                v2 = fmaxf(v2, 0.0f); v3 = fmaxf(v3, 0.0f);
            }
            *(float2*)&C[(size_t)r0 * ldc + col]       = make_float2(v0, v1);
            *(float2*)&C[(size_t)(r0 + 8) * ldc + col] = make_float2(v2, v3);
        }
    }
}

// ---------------------------------------------------------------------------
// GRU combine: belief = (1-z)*n + z*h
// ---------------------------------------------------------------------------
__global__ void gru_combine_kernel(const float* __restrict__ g, const float* __restrict__ h,
                                   const float* __restrict__ b_ir, const float* __restrict__ b_iz,
                                   const float* __restrict__ b_in, const float* __restrict__ b_hn,
                                   float* __restrict__ belief) {
    int i = blockIdx.x * blockDim.x + threadIdx.x;
    if (i >= BROWS * 200) return;
    int b = i / 200, j = i - b * 200;
    const float* gr = g + (size_t)b * 800;
    float r  = 1.0f / (1.0f + expf(-(gr[j]       + b_ir[j])));
    float z  = 1.0f / (1.0f + expf(-(gr[200 + j] + b_iz[j])));
    float nn = tanhf(gr[400 + j] + b_in[j] + r * (gr[600 + j] + b_hn[j]));
    float hv = h[i];
    belief[i] = (1.0f - z) * nn + z * hv;
}

// ---------------------------------------------------------------------------
// Distribution epilogue
// ---------------------------------------------------------------------------
__global__ void dist_kernel(const float* __restrict__ p, const float* __restrict__ eps,
                            float* __restrict__ st, float* __restrict__ mean,
                            float* __restrict__ stddev) {
    int i = blockIdx.x * blockDim.x + threadIdx.x;
    if (i >= BROWS * 100) return;
    int b = i / 100, d = i - b * 100;
    float m   = p[(size_t)b * 200 + d];
    float raw = p[(size_t)b * 200 + 100 + d];
    float sp  = (raw > 0.0f) ? (raw + log1pf(expf(-raw))) : log1pf(expf(raw));
    float s   = sp + 0.1f;
    mean[i]   = m;
    stddev[i] = s;
    st[i]     = m + s * eps[i];
}

// ---------------------------------------------------------------------------
extern "C" void kernel_launch(void* const* d_in, const int* in_sizes, int n_in,
                              void* d_out, int out_size) {
    const float* prev_state   = (const float*)d_in[0];
    const float* prev_action  = (const float*)d_in[1];
    const float* prev_belief  = (const float*)d_in[2];
    const float* observation  = (const float*)d_in[3];
    const float* nonterminals = (const float*)d_in[4];
    const float* W_sa = (const float*)d_in[5];  const float* b_sa = (const float*)d_in[6];
    const float* W_ir = (const float*)d_in[7];  const float* b_ir = (const float*)d_in[8];
    const float* W_iz = (const float*)d_in[9];  const float* b_iz = (const float*)d_in[10];
    const float* W_in = (const float*)d_in[11]; const float* b_in = (const float*)d_in[12];
    const float* W_hr = (const float*)d_in[13];
    const float* W_hz = (const float*)d_in[14];
    const float* W_hn = (const float*)d_in[15]; const float* b_hn = (const float*)d_in[16];
    const float* W_bp = (const float*)d_in[17]; const float* b_bp = (const float*)d_in[18];
    const float* W_sp = (const float*)d_in[19]; const float* b_sp = (const float*)d_in[20];
    const float* W_bq = (const float*)d_in[21]; const float* b_bq = (const float*)d_in[22];
    const float* W_sq = (const float*)d_in[23]; const float* b_sq = (const float*)d_in[24];

    float* out = (float*)d_out;

    float *h, *g, *hp, *p, *eps, *sm, *wgru;
    uint32_t *wp1, *wp2;
    cudaGetSymbolAddress((void**)&h,    g_h);
    cudaGetSymbolAddress((void**)&g,    g_g);
    cudaGetSymbolAddress((void**)&hp,   g_hp);
    cudaGetSymbolAddress((void**)&p,    g_p);
    cudaGetSymbolAddress((void**)&eps,  g_eps);
    cudaGetSymbolAddress((void**)&sm,   g_sm);
    cudaGetSymbolAddress((void**)&wgru, g_wgru);
    cudaGetSymbolAddress((void**)&wp1,  g_wp1);
    cudaGetSymbolAddress((void**)&wp2,  g_wp2);

    cudaFuncSetAttribute(gemm_kernel<true, true>,
                         cudaFuncAttributeMaxDynamicSharedMemorySize, SMEM_BYTES);
    cudaFuncSetAttribute(gemm_kernel<false, false>,
                         cudaFuncAttributeMaxDynamicSharedMemorySize, SMEM_BYTES);

    const size_t oBelief    = 0;
    const size_t oPriorSt   = (size_t)BROWS * 200;
    const size_t oPriorMean = (size_t)BROWS * 300;
    const size_t oPriorStd  = (size_t)BROWS * 400;
    const size_t oPostSt    = (size_t)BROWS * 500;
    const size_t oPostMean  = (size_t)BROWS * 600;
    const size_t oPostStd   = (size_t)BROWS * 700;

    const int MB = BROWS / BM;   // 512 row blocks

    // ---- fused prep (eps + premult + wgru pack) ----
    {
        int total = N_EPS + N_PM + N_WG;
        prep_kernel<<<(total + 255) / 256, 256>>>(
            eps, prev_state, nonterminals, sm,
            W_ir, W_iz, W_in, W_hr, W_hz, W_hn, wgru);
    }

    // ---- single segmented pack+split (fragment-order u64 planes) ----
    {
        PsplitArgs a;
        const float* Ws[6] = {W_sa, wgru, W_bp, W_sp, W_bq, W_sq};
        int Ks[6]   = {132, 400, 200, 200, 1224, 200};
        int Ns[6]   = {200, 800, 200, 200, 200, 200};
        int lds[6]  = {200, 800, 200, 200, 200, 200};
        int Kpad[6] = {160, 416, 224, 224, 1248, 224};
        uint32_t off[6] = {WP_SA, WP_GRU, WP_BP, WP_SP, WP_BQ, WP_SQ};
        uint32_t cum = 0;
        for (int i = 0; i < 6; i++) {
            a.W[i] = Ws[i]; a.K[i] = Ks[i]; a.N[i] = Ns[i];
            a.ldw[i] = lds[i]; a.off[i] = off[i];
            cum += (uint32_t)(Ns[i] * (Kpad[i] / 4));   // u64 entries
            a.cum[i] = cum;
        }
        psplit_all_kernel<<<((int)a.cum[5] + 255) / 256, 256>>>(a, wp1, wp2);
    }

    // 3) h = relu([sm, action] @ W_sa + b_sa)   (K=132)
    gemm_kernel<true, true><<<dim3(MB, 1), GTHREADS, SMEM_BYTES>>>(
        sm, prev_action, 100, 32, 132, 160, wp1 + WP_SA, wp2 + WP_SA, 200, b_sa, h, 200);

    // 4) g = [prev_belief, h] @ Wgru            (K=400, N=800)
    gemm_kernel<false, false><<<dim3(MB, 4), GTHREADS, SMEM_BYTES>>>(
        prev_belief, h, 200, 200, 400, 416, wp1 + WP_GRU, wp2 + WP_GRU, 800, nullptr, g, 800);

    // 5) new_belief
    gru_combine_kernel<<<(BROWS * 200 + 255) / 256, 256>>>(
        g, h, b_ir, b_iz, b_in, b_hn, out + oBelief);

    // 6) hp = relu(belief @ W_bp + b_bp)        (K=200)
    gemm_kernel<true, true><<<dim3(MB, 1), GTHREADS, SMEM_BYTES>>>(
        out + oBelief, out + oBelief, 200, 200, 200, 224, wp1 + WP_BP, wp2 + WP_BP, 200, b_bp, hp, 200);

    // 7) p = relu(hp @ W_sp + b_sp)             (K=200)
    gemm_kernel<true, true><<<dim3(MB, 1), GTHREADS, SMEM_BYTES>>>(
        hp, hp, 200, 200, 200, 224, wp1 + WP_SP, wp2 + WP_SP, 200, b_sp, p, 200);

    // 8) prior outputs
    dist_kernel<<<(BROWS * 100 + 255) / 256, 256>>>(
        p, eps, out + oPriorSt, out + oPriorMean, out + oPriorStd);

    // 9) hq = relu([belief, obs] @ W_bq + b_bq) (K=1224)
    gemm_kernel<true, true><<<dim3(MB, 1), GTHREADS, SMEM_BYTES>>>(
        out + oBelief, observation, 200, 1024, 1224, 1248, wp1 + WP_BQ, wp2 + WP_BQ, 200, b_bq, hp, 200);

    // 10) p = relu(hq @ W_sq + b_sq)            (K=200)
    gemm_kernel<true, true><<<dim3(MB, 1), GTHREADS, SMEM_BYTES>>>(
        hp, hp, 200, 200, 200, 224, wp1 + WP_SQ, wp2 + WP_SQ, 200, b_sq, p, 200);

    // 11) posterior outputs
    dist_kernel<<<(BROWS * 100 + 255) / 256, 256>>>(
        p, eps, out + oPostSt, out + oPostMean, out + oPostStd);

    (void)in_sizes; (void)n_in; (void)out_size;
}